// round 1
// baseline (speedup 1.0000x reference)
#include <cuda_runtime.h>
#include <math.h>

// Problem constants
#define DEPTH 12
#define E_DIM 256
#define F_DIM 128
#define H_DIM 8
#define HD 32
#define U_DIM 1000
#define I_DIM 1000
#define B_DIM 64
#define N_TOK 257            // 2F+1
#define M_ROWS (B_DIM * N_TOK)   // 16448 = 257*64, divisible by 64
#define FF_DIM 1024

// ---------------- scratch (device globals; no allocation allowed) -----------
__device__ float d_x[M_ROWS * E_DIM];
__device__ float d_h[M_ROWS * E_DIM];
__device__ float d_q[M_ROWS * E_DIM];
__device__ float d_k[M_ROWS * E_DIM];
__device__ float d_v[M_ROWS * E_DIM];
__device__ float d_o[M_ROWS * E_DIM];
__device__ float d_t[M_ROWS * FF_DIM];

// ---------------- embedding: x = concat(cls, xu, xi) + positions ------------
__global__ __launch_bounds__(256) void embed_kernel(
    const int* __restrict__ user, const int* __restrict__ item,
    const float* __restrict__ ut, const float* __restrict__ it,
    const float* __restrict__ cls, const float* __restrict__ pos,
    float* __restrict__ x)
{
    int n = blockIdx.x;          // 0..256
    int b = blockIdx.y;          // 0..63
    int e = threadIdx.x;         // 0..255
    float v;
    if (n == 0) {
        v = cls[e];
    } else if (n <= F_DIM) {
        int uid = user[b];
        v = ut[((size_t)e * U_DIM + uid) * F_DIM + (n - 1)];
    } else {
        int iid = item[b];
        v = it[((size_t)e * I_DIM + iid) * F_DIM + (n - 1 - F_DIM)];
    }
    x[((size_t)b * N_TOK + n) * E_DIM + e] = v + pos[(size_t)n * E_DIM + e];
}

// ---------------- layernorm over last dim (E=256), 1 block per row ----------
__device__ __forceinline__ float warp_sum(float v) {
    #pragma unroll
    for (int o = 16; o > 0; o >>= 1) v += __shfl_xor_sync(0xffffffffu, v, o);
    return v;
}

__global__ __launch_bounds__(256) void layernorm_kernel(
    const float* __restrict__ x, const float* __restrict__ g,
    const float* __restrict__ b, float* __restrict__ out)
{
    int row = blockIdx.x;
    int e = threadIdx.x;
    int w = e >> 5, lane = e & 31;
    float v = x[(size_t)row * E_DIM + e];
    __shared__ float sA[8], sB[8];
    float s = warp_sum(v);
    float ss = warp_sum(v * v);
    if (lane == 0) { sA[w] = s; sB[w] = ss; }
    __syncthreads();
    float tot = 0.f, tot2 = 0.f;
    #pragma unroll
    for (int i = 0; i < 8; i++) { tot += sA[i]; tot2 += sB[i]; }
    float mean = tot * (1.f / E_DIM);
    float var = tot2 * (1.f / E_DIM) - mean * mean;
    float rstd = rsqrtf(var + 1e-5f);
    out[(size_t)row * E_DIM + e] = (v - mean) * rstd * g[e] + b[e];
}

// ---------------- tiled SGEMM: C = A[MxK] @ W[KxN] + bias (+gelu|+res) ------
// BM=64, BN=64, BK=16, 256 threads, 4x4 per thread. M,N,K all multiples used.
__global__ __launch_bounds__(256) void sgemm_kernel(
    const float* __restrict__ A, const float* __restrict__ W,
    const float* __restrict__ bias, const float* __restrict__ res,
    float* __restrict__ C, int M, int K, int N, int gelu)
{
    __shared__ float As[16][68];
    __shared__ float Bs[16][68];

    int tid = threadIdx.x;
    int tx = tid & 15;          // 0..15
    int ty = tid >> 4;          // 0..15
    int br = blockIdx.y * 64;
    int bc = blockIdx.x * 64;

    int arow = tid >> 2;        // 0..63
    int acol4 = tid & 3;        // 0..3 (float4 within K-tile)
    int brow = tid >> 4;        // 0..15
    int bcol4 = tid & 15;       // 0..15

    float acc[4][4];
    #pragma unroll
    for (int i = 0; i < 4; i++)
        #pragma unroll
        for (int j = 0; j < 4; j++) acc[i][j] = 0.f;

    const float* Aptr = A + (size_t)(br + arow) * K + acol4 * 4;
    const float* Wptr = W + (size_t)brow * N + bc + bcol4 * 4;

    for (int k0 = 0; k0 < K; k0 += 16) {
        float4 a = *(const float4*)(Aptr + k0);
        float4 bvld = *(const float4*)(Wptr + (size_t)k0 * N);
        As[acol4 * 4 + 0][arow] = a.x;
        As[acol4 * 4 + 1][arow] = a.y;
        As[acol4 * 4 + 2][arow] = a.z;
        As[acol4 * 4 + 3][arow] = a.w;
        *(float4*)&Bs[brow][bcol4 * 4] = bvld;
        __syncthreads();

        #pragma unroll
        for (int kk = 0; kk < 16; kk++) {
            float4 av = *(const float4*)&As[kk][ty * 4];
            float4 bv = *(const float4*)&Bs[kk][tx * 4];
            float ar[4] = {av.x, av.y, av.z, av.w};
            float brr[4] = {bv.x, bv.y, bv.z, bv.w};
            #pragma unroll
            for (int i = 0; i < 4; i++)
                #pragma unroll
                for (int j = 0; j < 4; j++)
                    acc[i][j] = fmaf(ar[i], brr[j], acc[i][j]);
        }
        __syncthreads();
    }

    float4 b4 = *(const float4*)&bias[bc + tx * 4];
    float bb[4] = {b4.x, b4.y, b4.z, b4.w};
    #pragma unroll
    for (int i = 0; i < 4; i++) {
        size_t row = (size_t)(br + ty * 4 + i);
        float o[4];
        #pragma unroll
        for (int j = 0; j < 4; j++) {
            float v = acc[i][j] + bb[j];
            if (gelu) v = 0.5f * v * (1.0f + erff(v * 0.70710678118654752f));
            o[j] = v;
        }
        if (res) {
            float4 r = *(const float4*)&res[row * N + bc + tx * 4];
            o[0] += r.x; o[1] += r.y; o[2] += r.z; o[3] += r.w;
        }
        float4 ov = {o[0], o[1], o[2], o[3]};
        *(float4*)&C[row * N + bc + tx * 4] = ov;
    }
}

// ---------------- attention: one block per (head, batch) --------------------
// energy = q.k (no prescale); att = softmax(energy)/sqrt(E); o = att @ v
__global__ __launch_bounds__(256) void attention_kernel(
    const float* __restrict__ Q, const float* __restrict__ K,
    const float* __restrict__ V, float* __restrict__ O)
{
    int h = blockIdx.x;
    int b = blockIdx.y;
    __shared__ float Ks[N_TOK * 33];
    __shared__ float qs[8 * 32];

    int tid = threadIdx.x;
    int w = tid >> 5, lane = tid & 31;
    const size_t base = ((size_t)b * N_TOK) * E_DIM + h * HD;

    // load K tile into padded smem
    for (int idx = tid; idx < N_TOK * 32; idx += 256) {
        int k = idx >> 5, d = idx & 31;
        Ks[k * 33 + d] = K[base + (size_t)k * E_DIM + d];
    }
    __syncthreads();

    for (int qi = w; qi < N_TOK; qi += 8) {
        qs[w * 32 + lane] = Q[base + (size_t)qi * E_DIM + lane];
        __syncwarp();

        float e[9];
        #pragma unroll
        for (int j = 0; j < 9; j++) {
            int k = j * 32 + lane;
            float s;
            if (k < N_TOK) {
                s = 0.f;
                #pragma unroll
                for (int d = 0; d < 32; d++)
                    s = fmaf(qs[w * 32 + d], Ks[k * 33 + d], s);
            } else {
                s = -INFINITY;
            }
            e[j] = s;
        }
        float m = e[0];
        #pragma unroll
        for (int j = 1; j < 9; j++) m = fmaxf(m, e[j]);
        #pragma unroll
        for (int o = 16; o > 0; o >>= 1) m = fmaxf(m, __shfl_xor_sync(0xffffffffu, m, o));

        float p[9]; float sum = 0.f;
        #pragma unroll
        for (int j = 0; j < 9; j++) {
            int k = j * 32 + lane;
            p[j] = (k < N_TOK) ? __expf(e[j] - m) : 0.f;
            sum += p[j];
        }
        sum = warp_sum(sum);
        float scale = 1.f / (sum * 16.0f);   // /sqrt(E) applied AFTER softmax

        // o_d (d = lane) = sum_k p_k * V[k][d], V streamed from L1
        const float* Vb = V + base + lane;
        float acc = 0.f;
        #pragma unroll
        for (int j = 0; j < 8; j++) {
            #pragma unroll
            for (int kk = 0; kk < 32; kk++) {
                float a = __shfl_sync(0xffffffffu, p[j], kk);
                acc = fmaf(a, __ldg(Vb + (size_t)(j * 32 + kk) * E_DIM), acc);
            }
        }
        {   // tail key 256 (valid only on lane 0's p[8])
            float a = __shfl_sync(0xffffffffu, p[8], 0);
            acc = fmaf(a, __ldg(Vb + (size_t)256 * E_DIM), acc);
        }
        O[base + (size_t)qi * E_DIM + lane] = acc * scale;
    }
}

// ---------------- mean-pool + head LN + linear -------------------------------
__global__ __launch_bounds__(256) void pool_head_kernel(
    const float* __restrict__ x, const float* __restrict__ g,
    const float* __restrict__ b, const float* __restrict__ W,
    const float* __restrict__ bias, float* __restrict__ out)
{
    int bb = blockIdx.x;
    int e = threadIdx.x;
    int w = e >> 5, lane = e & 31;
    float s = 0.f;
    const float* xb = x + (size_t)bb * N_TOK * E_DIM + e;
    for (int n = 0; n < N_TOK; n++) s += xb[(size_t)n * E_DIM];
    float pooled = s * (1.0f / N_TOK);

    __shared__ float sA[8], sB[8];
    float s1 = warp_sum(pooled);
    float s2 = warp_sum(pooled * pooled);
    if (lane == 0) { sA[w] = s1; sB[w] = s2; }
    __syncthreads();
    float tot = 0.f, tot2 = 0.f;
    #pragma unroll
    for (int i = 0; i < 8; i++) { tot += sA[i]; tot2 += sB[i]; }
    float mean = tot * (1.f / E_DIM);
    float var = tot2 * (1.f / E_DIM) - mean * mean;
    float rstd = rsqrtf(var + 1e-5f);
    float y = (pooled - mean) * rstd * g[e] + b[e];
    float t = y * W[e];
    __syncthreads();
    float t1 = warp_sum(t);
    if (lane == 0) sA[w] = t1;
    __syncthreads();
    if (e == 0) {
        float tot3 = 0.f;
        #pragma unroll
        for (int i = 0; i < 8; i++) tot3 += sA[i];
        out[bb] = tot3 + bias[0];
    }
}

// ---------------- driver -----------------------------------------------------
extern "C" void kernel_launch(void* const* d_in, const int* in_sizes, int n_in,
                              void* d_out, int out_size)
{
    const int*   user    = (const int*)  d_in[0];
    const int*   item    = (const int*)  d_in[1];
    const float* ut      = (const float*)d_in[2];
    const float* it      = (const float*)d_in[3];
    const float* cls     = (const float*)d_in[4];
    const float* pos     = (const float*)d_in[5];
    const float* ln1_g   = (const float*)d_in[6];
    const float* ln1_b   = (const float*)d_in[7];
    const float* Wq      = (const float*)d_in[8];
    const float* bq      = (const float*)d_in[9];
    const float* Wk      = (const float*)d_in[10];
    const float* bk      = (const float*)d_in[11];
    const float* Wv      = (const float*)d_in[12];
    const float* bv      = (const float*)d_in[13];
    const float* Wo      = (const float*)d_in[14];
    const float* bo      = (const float*)d_in[15];
    const float* ln2_g   = (const float*)d_in[16];
    const float* ln2_b   = (const float*)d_in[17];
    const float* W1      = (const float*)d_in[18];
    const float* b1      = (const float*)d_in[19];
    const float* W2      = (const float*)d_in[20];
    const float* b2      = (const float*)d_in[21];
    const float* head_g  = (const float*)d_in[22];
    const float* head_b  = (const float*)d_in[23];
    const float* head_W  = (const float*)d_in[24];
    const float* head_bi = (const float*)d_in[25];

    float *x, *h, *q, *k, *v, *o, *t;
    cudaGetSymbolAddress((void**)&x, d_x);
    cudaGetSymbolAddress((void**)&h, d_h);
    cudaGetSymbolAddress((void**)&q, d_q);
    cudaGetSymbolAddress((void**)&k, d_k);
    cudaGetSymbolAddress((void**)&v, d_v);
    cudaGetSymbolAddress((void**)&o, d_o);
    cudaGetSymbolAddress((void**)&t, d_t);

    embed_kernel<<<dim3(N_TOK, B_DIM), 256>>>(user, item, ut, it, cls, pos, x);

    const dim3 g256(E_DIM / 64, M_ROWS / 64);     // (4, 257)
    const dim3 g1024(FF_DIM / 64, M_ROWS / 64);   // (16, 257)

    for (int l = 0; l < DEPTH; l++) {
        size_t eOff  = (size_t)l * E_DIM;
        size_t eeOff = (size_t)l * E_DIM * E_DIM;
        size_t ffOff = (size_t)l * E_DIM * FF_DIM;

        layernorm_kernel<<<M_ROWS, 256>>>(x, ln1_g + eOff, ln1_b + eOff, h);

        sgemm_kernel<<<g256, 256>>>(h, Wq + eeOff, bq + eOff, nullptr, q,
                                    M_ROWS, E_DIM, E_DIM, 0);
        sgemm_kernel<<<g256, 256>>>(h, Wk + eeOff, bk + eOff, nullptr, k,
                                    M_ROWS, E_DIM, E_DIM, 0);
        sgemm_kernel<<<g256, 256>>>(h, Wv + eeOff, bv + eOff, nullptr, v,
                                    M_ROWS, E_DIM, E_DIM, 0);

        attention_kernel<<<dim3(H_DIM, B_DIM), 256>>>(q, k, v, o);

        // x = x + (o @ Wo + bo)
        sgemm_kernel<<<g256, 256>>>(o, Wo + eeOff, bo + eOff, x, x,
                                    M_ROWS, E_DIM, E_DIM, 0);

        layernorm_kernel<<<M_ROWS, 256>>>(x, ln2_g + eOff, ln2_b + eOff, h);

        // t = gelu(h @ W1 + b1)
        sgemm_kernel<<<g1024, 256>>>(h, W1 + ffOff, b1 + (size_t)l * FF_DIM,
                                     nullptr, t, M_ROWS, E_DIM, FF_DIM, 1);
        // x = x + (t @ W2 + b2)
        sgemm_kernel<<<g256, 256>>>(t, W2 + ffOff, b2 + eOff, x, x,
                                    M_ROWS, FF_DIM, E_DIM, 0);
    }

    pool_head_kernel<<<B_DIM, 256>>>(x, head_g, head_b, head_W, head_bi,
                                     (float*)d_out);
}